// round 14
// baseline (speedup 1.0000x reference)
#include <cuda_runtime.h>
#include <mma.h>
#include <math.h>

using namespace nvcuda;

#define BB 64
#define LL 50
#define HH 1024
#define VV 50257
#define NBLK ((VV + 127) / 128)   // 393 logits blocks

// ------------------------ scratch ------------------------
__device__ __align__(16) float g_x[BB * HH];
__device__ __align__(16) float g_q[BB * HH];
__device__ __align__(16) float g_scores[BB * LL];
__device__ __align__(16) float g_wenc[BB * 2 * HH];
__device__ __align__(16) float g_hnext[BB * HH];
__device__ __align__(16) float g_lse[BB];
__device__ __align__(16) float g_lsp[BB * NBLK * 2];   // per-block (max, sumexp) partials
// split-K partials
__device__ __align__(16) float g_partq[4 * BB * HH];
__device__ __align__(16) float g_partqk[4 * BB * 2 * HH];
__device__ __align__(16) float g_partc[8 * BB * HH];
__device__ __align__(16) float g_partg[8 * BB * 4 * HH];

// ------------------------ cp.async helpers ------------------------
__device__ __forceinline__ unsigned smem_u32(const void* p) {
    return (unsigned)__cvta_generic_to_shared(p);
}
__device__ __forceinline__ void cp16(unsigned dst, const void* src) {
    asm volatile("cp.async.cg.shared.global [%0], [%1], 16;\n" :: "r"(dst), "l"(src));
}
__device__ __forceinline__ void cp4(unsigned dst, const void* src, int sz) {
    asm volatile("cp.async.ca.shared.global [%0], [%1], 4, %2;\n" :: "r"(dst), "l"(src), "r"(sz));
}
__device__ __forceinline__ void cp_commit() { asm volatile("cp.async.commit_group;\n"); }
template <int N> __device__ __forceinline__ void cp_wait() {
    asm volatile("cp.async.wait_group %0;\n" :: "n"(N));
}

// ------------------------ embedding gather ------------------------
__global__ void __launch_bounds__(256) k_gather(const int* __restrict__ idx,
                                                const float* __restrict__ emb) {
    int b = blockIdx.x;
    const float4* src = (const float4*)(emb + (size_t)idx[b] * HH);
    float4* dst = (float4*)(g_x + b * HH);
    if (threadIdx.x < HH / 4) dst[threadIdx.x] = src[threadIdx.x];
}

// ------------------------ q = sum(4 parts) + bias ------------------------
__global__ void __launch_bounds__(256) k_qbias(const float* __restrict__ query_b) {
    int b = blockIdx.x;
    int j = blockIdx.y * 256 + threadIdx.x;
    float s = query_b[j];
#pragma unroll
    for (int p = 0; p < 4; p++) s += g_partq[p * BB * HH + b * HH + j];
    g_q[b * HH + j] = s;
}

// ------------------------ pipelined M=64 tf32 GEMM with split-K ------------------------
// C[64,N] = [A1 | A2] @ [B1 ; B2].  !B_NK: B row-major [K,N]; B_NK: B is [N,K] (B^T mult).
// gridDim.y = KS splits; split ky writes partials to C + ky*64*ldc.
// ebias (optional): added to C in the staged-epilogue path. lsp (optional): per-block
// per-row (max, sumexp) partials for fused log-softmax pass 1.
template <int BN, int S, bool B_NK>
__global__ void __launch_bounds__(256) gemm_pipe(
    const float* __restrict__ A1, const float* __restrict__ A2, int K1, int Ktot,
    const float* __restrict__ B1, const float* __restrict__ B2, int ldb1, int ldb2,
    float* __restrict__ C, int ldc, int N,
    const float* __restrict__ ebias, float* __restrict__ lsp) {
    constexpr int BK  = 16;
    constexpr int AP  = 20;
    constexpr int BPL = BN + 4;     // KN row stride
    constexpr int BNS = 20;         // NK row stride
    constexpr int BSTG = B_NK ? (BN * BNS) : (BK * BPL);
    constexpr int TN = BN / 32;

    extern __shared__ char dsm[];
    float* sA = (float*)dsm;
    float* sB = (float*)(dsm + (size_t)S * 64 * AP * 4);

    const int tid = threadIdx.x, w = tid >> 5, lane = tid & 31;
    const int wm = w & 3, wn = w >> 2;
    const int n0 = blockIdx.x * BN;
    const int Tall = Ktot / BK;
    const int Tper = Tall / gridDim.y;
    const int t0 = blockIdx.y * Tper;
    const bool fullN = (n0 + BN) <= N;
    const bool bAligned = (((ldb1 | ldb2) & 3) == 0);
    C += (size_t)blockIdx.y * 64 * ldc;

    auto issue = [&](int t) {
        int k0 = t * BK;
        const float* Aseg; const float* Bseg; int lda, ldb, kk;
        if (k0 < K1) { Aseg = A1; Bseg = B1; lda = K1;        ldb = ldb1; kk = k0; }
        else         { Aseg = A2; Bseg = B2; lda = Ktot - K1; ldb = ldb2; kk = k0 - K1; }
        int buf = (t - t0) % S;
        int ar = tid >> 2, av = (tid & 3) * 4;
        cp16(smem_u32(&sA[buf * 64 * AP + ar * AP + av]), Aseg + (size_t)ar * lda + kk + av);
        float* sBb = &sB[buf * BSTG];
        if (!B_NK) {
            if (bAligned) {
                constexpr int NV = BN / 4;
                constexpr int TOT = BK * NV;
#pragma unroll
                for (int i = tid; i < TOT; i += 256) {
                    int r = i / NV, c = (i % NV) * 4;
                    cp16(smem_u32(&sBb[r * BPL + c]), Bseg + (size_t)(kk + r) * ldb + n0 + c);
                }
            } else if (fullN) {
                constexpr int TOT = BK * BN;
#pragma unroll
                for (int i = tid; i < TOT; i += 256) {
                    int r = i / BN, c = i % BN;
                    cp4(smem_u32(&sBb[r * BPL + c]), Bseg + (size_t)(kk + r) * ldb + n0 + c, 4);
                }
            } else {
                constexpr int TOT = BK * BN;
#pragma unroll
                for (int i = tid; i < TOT; i += 256) {
                    int r = i / BN, c = i % BN;
                    int n = n0 + c;
                    int ok = n < N;
                    const float* src = Bseg + (size_t)(kk + r) * ldb + (ok ? n : 0);
                    cp4(smem_u32(&sBb[r * BPL + c]), src, ok ? 4 : 0);
                }
            }
        } else {
            constexpr int TOT = BN * 4;
#pragma unroll
            for (int i = tid; i < TOT; i += 256) {
                int r = i >> 2, c = (i & 3) * 4;
                int n = n0 + r;
                cp16(smem_u32(&sBb[r * BNS + c]), Bseg + (size_t)n * ldb + kk + c);
            }
        }
    };

    wmma::fragment<wmma::matrix_a, 16, 16, 8, wmma::precision::tf32, wmma::row_major> fa;
    wmma::fragment<wmma::accumulator, 16, 16, 8, float> fc[TN];
#pragma unroll
    for (int t = 0; t < TN; t++) wmma::fill_fragment(fc[t], 0.f);

#pragma unroll
    for (int p = 0; p < S - 1; p++) { if (p < Tper) issue(t0 + p); cp_commit(); }

    for (int t = t0; t < t0 + Tper; t++) {
        cp_wait<S - 2>();
        __syncthreads();
        if (t + S - 1 < t0 + Tper) issue(t + S - 1);
        cp_commit();
        int buf = (t - t0) % S;
        float* sAb = &sA[buf * 64 * AP];
        float* sBb = &sB[buf * BSTG];
#pragma unroll
        for (int ks = 0; ks < 2; ks++) {
            wmma::load_matrix_sync(fa, &sAb[wm * 16 * AP + ks * 8], AP);
#pragma unroll
            for (int i = 0; i < fa.num_elements; i++) fa.x[i] = wmma::__float_to_tf32(fa.x[i]);
#pragma unroll
            for (int tt = 0; tt < TN; tt++) {
                int ns = wn * (BN / 2) + tt * 16;
                if (!B_NK) {
                    wmma::fragment<wmma::matrix_b, 16, 16, 8, wmma::precision::tf32, wmma::row_major> fb;
                    wmma::load_matrix_sync(fb, &sBb[ks * 8 * BPL + ns], BPL);
#pragma unroll
                    for (int i = 0; i < fb.num_elements; i++) fb.x[i] = wmma::__float_to_tf32(fb.x[i]);
                    wmma::mma_sync(fc[tt], fa, fb, fc[tt]);
                } else {
                    wmma::fragment<wmma::matrix_b, 16, 16, 8, wmma::precision::tf32, wmma::col_major> fb;
                    wmma::load_matrix_sync(fb, &sBb[ns * BNS + ks * 8], BNS);
#pragma unroll
                    for (int i = 0; i < fb.num_elements; i++) fb.x[i] = wmma::__float_to_tf32(fb.x[i]);
                    wmma::mma_sync(fc[tt], fa, fb, fc[tt]);
                }
            }
        }
    }

    __syncthreads();
    const bool ldc_ok = (ldc & 3) == 0;
    if (ldc_ok && fullN) {
#pragma unroll
        for (int tt = 0; tt < TN; tt++) {
            int nc = n0 + wn * (BN / 2) + tt * 16;
            wmma::store_matrix_sync(&C[(size_t)(wm * 16) * ldc + nc], fc[tt], ldc, wmma::mem_row_major);
        }
    } else {
        // staged epilogue: sC spans sA+sB (both dead)
        constexpr int CP = BN + 4;
        float* sC = sA;
        float* sb = sC + 64 * CP;
#pragma unroll
        for (int tt = 0; tt < TN; tt++) {
            int ns = wn * (BN / 2) + tt * 16;
            wmma::store_matrix_sync(&sC[(size_t)(wm * 16) * CP + ns], fc[tt], CP, wmma::mem_row_major);
        }
        if (ebias) {
            for (int c = tid; c < BN; c += 256) sb[c] = (n0 + c < N) ? ebias[n0 + c] : 0.f;
        }
        __syncthreads();
        for (int i = tid; i < 64 * BN; i += 256) {
            int r = i / BN, c = i % BN;
            int n = n0 + c;
            float v = sC[r * CP + c] + (ebias ? sb[c] : 0.f);
            sC[r * CP + c] = v;
            if (n < N) C[(size_t)r * ldc + n] = v;
        }
        if (lsp) {
            __syncthreads();
            const int nv = min(BN, N - n0);
#pragma unroll
            for (int rr = 0; rr < 8; rr++) {
                int r = w * 8 + rr;
                float mx = -1e30f;
                for (int c = lane; c < nv; c += 32) mx = fmaxf(mx, sC[r * CP + c]);
#pragma unroll
                for (int o = 16; o > 0; o >>= 1) mx = fmaxf(mx, __shfl_xor_sync(0xffffffffu, mx, o));
                float sm = 0.f;
                for (int c = lane; c < nv; c += 32) sm += __expf(sC[r * CP + c] - mx);
#pragma unroll
                for (int o = 16; o > 0; o >>= 1) sm += __shfl_xor_sync(0xffffffffu, sm, o);
                if (lane == 0) {
                    size_t o2 = ((size_t)r * gridDim.x + blockIdx.x) * 2;
                    lsp[o2] = mx; lsp[o2 + 1] = sm;
                }
            }
        }
    }
}

// ------------------------ attention scores (sums 4 qk parts) ------------------------
__global__ void __launch_bounds__(256) k_scores(const float* __restrict__ enc) {
    int b = blockIdx.x;
    int tid = threadIdx.x, w = tid >> 5, lane = tid & 31;
    __shared__ __align__(16) float sq[2 * HH];
    for (int j = tid; j < 2 * HH; j += 256) {
        float s = 0.f;
#pragma unroll
        for (int p = 0; p < 4; p++) s += g_partqk[p * BB * 2 * HH + b * 2 * HH + j];
        sq[j] = s;
    }
    __syncthreads();

    for (int ll = w; ll < 10; ll += 8) {
        int l = blockIdx.y * 10 + ll;
        const float* e = enc + ((size_t)b * LL + l) * 2 * HH;
        float acc = 0.f;
        for (int j = lane * 4; j < 2 * HH; j += 128) {
            float4 ev = *(const float4*)(e + j);
            float4 qv = *(const float4*)(sq + j);
            acc += ev.x * qv.x + ev.y * qv.y + ev.z * qv.z + ev.w * qv.w;
        }
#pragma unroll
        for (int o = 16; o > 0; o >>= 1) acc += __shfl_xor_sync(0xffffffffu, acc, o);
        if (lane == 0) g_scores[b * LL + l] = acc * (1.f / HH);
    }
}

// ------------------------ weighted encoder sum with fused softmax ------------------------
__global__ void __launch_bounds__(256) k_wenc(const float* __restrict__ enc,
                                              float* __restrict__ out_attn) {
    int b = blockIdx.x;
    int tid = threadIdx.x;
    int j = blockIdx.y * 256 + tid;
    __shared__ float at[LL];
    if (tid < 32) {
        float v0 = (tid < LL) ? g_scores[b * LL + tid] : -1e30f;
        float v1 = (tid + 32 < LL) ? g_scores[b * LL + tid + 32] : -1e30f;
        float m = fmaxf(v0, v1);
#pragma unroll
        for (int o = 16; o > 0; o >>= 1) m = fmaxf(m, __shfl_xor_sync(0xffffffffu, m, o));
        float e0 = (tid < LL) ? expf(v0 - m) : 0.f;
        float e1 = (tid + 32 < LL) ? expf(v1 - m) : 0.f;
        float s = e0 + e1;
#pragma unroll
        for (int o = 16; o > 0; o >>= 1) s += __shfl_xor_sync(0xffffffffu, s, o);
        float inv = 1.f / s;
        if (tid < LL) {
            at[tid] = e0 * inv;
            if (blockIdx.y == 0 && out_attn) out_attn[b * LL + tid] = e0 * inv;
        }
        if (tid + 32 < LL) {
            at[tid + 32] = e1 * inv;
            if (blockIdx.y == 0 && out_attn) out_attn[b * LL + tid + 32] = e1 * inv;
        }
    }
    __syncthreads();
    const float* e = enc + (size_t)b * LL * 2 * HH + j;
    float acc = 0.f;
#pragma unroll 5
    for (int l = 0; l < LL; l++) acc += at[l] * e[(size_t)l * 2 * HH];
    g_wenc[b * 2 * HH + j] = acc;
}

// ------------------------ LSTM elementwise (sums 8 split-K parts, folds biases) ------------------------
__global__ void __launch_bounds__(256) k_lstm(const float* __restrict__ value_b,
                                              const float* __restrict__ b_x,
                                              const float* __restrict__ b_h,
                                              float* __restrict__ out_h) {
    int b = blockIdx.x;
    int h = blockIdx.y * 256 + threadIdx.x;
    float gf = b_x[h]          + b_h[h];
    float gi = b_x[HH + h]     + b_h[HH + h];
    float gc = b_x[2 * HH + h] + b_h[2 * HH + h];
    float go = b_x[3 * HH + h] + b_h[3 * HH + h];
#pragma unroll
    for (int p = 0; p < 8; p++) {
        const float* g = g_partg + (size_t)p * BB * 4 * HH + b * 4 * HH;
        gf += g[h]; gi += g[HH + h]; gc += g[2 * HH + h]; go += g[3 * HH + h];
    }
    float cp = value_b[h];
#pragma unroll
    for (int p = 0; p < 8; p++) cp += g_partc[p * BB * HH + b * HH + h];

    float f  = 1.f / (1.f + expf(-gf));
    float ig = 1.f / (1.f + expf(-gi));
    float cb = tanhf(gc);
    float o  = 1.f / (1.f + expf(-go));
    float c  = f * cp + ig * cb;
    float hn = o * tanhf(c);
    g_hnext[b * HH + h] = hn;
    if (out_h) out_h[b * HH + h] = hn;
}

// ------------------------ log-softmax reduce over per-block partials ------------------------
__global__ void __launch_bounds__(128) k_lsmred() {
    int b = blockIdx.x, tid = threadIdx.x;
    __shared__ float red[128];
    float M = -1e30f;
    for (int i = tid; i < NBLK; i += 128) M = fmaxf(M, g_lsp[((size_t)b * NBLK + i) * 2]);
    red[tid] = M; __syncthreads();
    for (int s = 64; s > 0; s >>= 1) { if (tid < s) red[tid] = fmaxf(red[tid], red[tid + s]); __syncthreads(); }
    M = red[0]; __syncthreads();
    float S = 0.f;
    for (int i = tid; i < NBLK; i += 128) {
        size_t o2 = ((size_t)b * NBLK + i) * 2;
        S += g_lsp[o2 + 1] * __expf(g_lsp[o2] - M);
    }
    red[tid] = S; __syncthreads();
    for (int s = 64; s > 0; s >>= 1) { if (tid < s) red[tid] += red[tid + s]; __syncthreads(); }
    if (tid == 0) g_lse[b] = M + logf(red[0]);
}

// ------------------------ log-softmax apply (bias already in logits) ------------------------
#define LSM_CH 6283
__global__ void __launch_bounds__(256) k_lsm2(float* __restrict__ logits) {
    int b = blockIdx.x, c = blockIdx.y, tid = threadIdx.x;
    float lse = g_lse[b];
    int start = c * LSM_CH, end = min(start + LSM_CH, VV);
    float* row = logits + (size_t)b * VV;
    for (int v = start + tid; v < end; v += 256) row[v] -= lse;
}

// ------------------------ launch ------------------------
extern "C" void kernel_launch(void* const* d_in, const int* in_sizes, int n_in,
                              void* d_out, int out_size) {
    (void)in_sizes; (void)n_in;
    const int*   idx     = (const int*)  d_in[0];
    const float* h_prev  = (const float*)d_in[1];
    const float* enc     = (const float*)d_in[2];
    const float* emb     = (const float*)d_in[3];
    const float* w_x     = (const float*)d_in[4];
    const float* b_x     = (const float*)d_in[5];
    const float* w_h     = (const float*)d_in[6];
    const float* b_h     = (const float*)d_in[7];
    const float* key_w   = (const float*)d_in[8];
    const float* value_w = (const float*)d_in[10];
    const float* value_b = (const float*)d_in[11];
    const float* query_w = (const float*)d_in[12];
    const float* query_b = (const float*)d_in[13];
    const float* out_w   = (const float*)d_in[14];
    const float* out_b   = (const float*)d_in[15];
    // d_in[9] = key_b: dropped — softmax is shift-invariant in the constant q·key_b.

    float* out      = (float*)d_out;
    float* out_logp = out;
    float* out_h    = nullptr;
    float* out_attn = nullptr;
    long long need = (long long)BB * VV + (long long)BB * HH + (long long)BB * LL;
    if ((long long)out_size >= need) {
        out_h    = out + (size_t)BB * VV;
        out_attn = out_h + (size_t)BB * HH;
    }

    float *p_x, *p_q, *p_wenc, *p_hnext, *p_partq, *p_partqk, *p_partc, *p_partg, *p_lsp;
    cudaGetSymbolAddress((void**)&p_x,      g_x);
    cudaGetSymbolAddress((void**)&p_q,      g_q);
    cudaGetSymbolAddress((void**)&p_wenc,   g_wenc);
    cudaGetSymbolAddress((void**)&p_hnext,  g_hnext);
    cudaGetSymbolAddress((void**)&p_partq,  g_partq);
    cudaGetSymbolAddress((void**)&p_partqk, g_partqk);
    cudaGetSymbolAddress((void**)&p_partc,  g_partc);
    cudaGetSymbolAddress((void**)&p_partg,  g_partg);
    cudaGetSymbolAddress((void**)&p_lsp,    g_lsp);

    constexpr int S = 4;
    const size_t smA      = (size_t)S * 64 * 20 * 4;
    const size_t sm_kn64  = smA + (size_t)S * 16 * 68 * 4;    // 37888
    const size_t sm_nk64  = smA + (size_t)S * 64 * 20 * 4;    // 40960
    const size_t sm_kn128 = smA + (size_t)S * 16 * 132 * 4;   // 54272

    cudaFuncSetAttribute(gemm_pipe<64, S, false>,  cudaFuncAttributeMaxDynamicSharedMemorySize, (int)sm_kn64);
    cudaFuncSetAttribute(gemm_pipe<64, S, true>,   cudaFuncAttributeMaxDynamicSharedMemorySize, (int)sm_nk64);
    cudaFuncSetAttribute(gemm_pipe<128, S, false>, cudaFuncAttributeMaxDynamicSharedMemorySize, (int)sm_kn128);

    k_gather<<<BB, 256>>>(idx, emb);

    // q partials = h_prev @ query_w  (split-K 4)
    gemm_pipe<64, S, false><<<dim3(HH / 64, 4), 256, sm_kn64>>>(
        h_prev, h_prev, HH, HH, query_w, query_w, HH, HH, p_partq, HH, HH, nullptr, nullptr);
    k_qbias<<<dim3(BB, 4), 256>>>(query_b);

    // qk partials = q @ key_w^T  (split-K 4)
    gemm_pipe<64, S, true><<<dim3((2 * HH) / 64, 4), 256, sm_nk64>>>(
        p_q, p_q, HH, HH, key_w, key_w, HH, HH, p_partqk, 2 * HH, 2 * HH, nullptr, nullptr);
    // scores (sums 4 qk parts) -> wenc with fused softmax
    k_scores<<<dim3(BB, 5), 256>>>(enc);
    k_wenc<<<dim3(BB, 8), 256>>>(enc, out_attn);

    // cprev partials = wenc @ value_w  (split-K 8)
    gemm_pipe<64, S, false><<<dim3(HH / 64, 8), 256, sm_kn64>>>(
        p_wenc, p_wenc, 2 * HH, 2 * HH, value_w, value_w, HH, HH, p_partc, HH, HH, nullptr, nullptr);
    // gates partials = [x | h_prev] @ [w_x ; w_h]  (split-K 8)
    gemm_pipe<64, S, false><<<dim3((4 * HH) / 64, 8), 256, sm_kn64>>>(
        p_x, h_prev, HH, 2 * HH, w_x, w_h, 4 * HH, 4 * HH, p_partg, 4 * HH, 4 * HH, nullptr, nullptr);
    k_lstm<<<dim3(BB, 4), 256>>>(value_b, b_x, b_h, out_h);

    // logits = h_next @ out_w + out_b, with fused log-softmax pass 1 in epilogue
    gemm_pipe<128, S, false><<<dim3(NBLK, 1), 256, sm_kn128>>>(
        p_hnext, p_hnext, HH, HH, out_w, out_w, VV, VV, out_logp, VV, VV, out_b, p_lsp);
    k_lsmred<<<BB, 128>>>();
    k_lsm2<<<dim3(BB, 8), 256>>>(out_logp);
}

// round 15
// speedup vs baseline: 1.0902x; 1.0902x over previous
#include <cuda_runtime.h>
#include <mma.h>
#include <math.h>

using namespace nvcuda;

#define BB 64
#define LL 50
#define HH 1024
#define VV 50257
#define NBLK ((VV + 127) / 128)   // 393 logits blocks

// ------------------------ scratch ------------------------
__device__ __align__(16) float g_x[BB * HH];
__device__ __align__(16) float g_q[BB * HH];
__device__ __align__(16) float g_scores[BB * LL];
__device__ __align__(16) float g_attn[BB * LL];
__device__ __align__(16) float g_wenc[BB * 2 * HH];
__device__ __align__(16) float g_hnext[BB * HH];
__device__ __align__(16) float g_lse[BB];
__device__ __align__(16) float g_lsp[BB * NBLK * 2];
// split-K partials
__device__ __align__(16) float g_partq[4 * BB * HH];
__device__ __align__(16) float g_partqk[4 * BB * 2 * HH];
__device__ __align__(16) float g_partc[8 * BB * HH];
__device__ __align__(16) float g_partg[8 * BB * 4 * HH];

// ------------------------ cp.async helpers ------------------------
__device__ __forceinline__ unsigned smem_u32(const void* p) {
    return (unsigned)__cvta_generic_to_shared(p);
}
__device__ __forceinline__ void cp16(unsigned dst, const void* src) {
    asm volatile("cp.async.cg.shared.global [%0], [%1], 16;\n" :: "r"(dst), "l"(src));
}
__device__ __forceinline__ void cp4(unsigned dst, const void* src, int sz) {
    asm volatile("cp.async.ca.shared.global [%0], [%1], 4, %2;\n" :: "r"(dst), "l"(src), "r"(sz));
}
__device__ __forceinline__ void cp_commit() { asm volatile("cp.async.commit_group;\n"); }
template <int N> __device__ __forceinline__ void cp_wait() {
    asm volatile("cp.async.wait_group %0;\n" :: "n"(N));
}

// ------------------------ embedding gather ------------------------
__global__ void __launch_bounds__(256) k_gather(const int* __restrict__ idx,
                                                const float* __restrict__ emb) {
    int b = blockIdx.x;
    const float4* src = (const float4*)(emb + (size_t)idx[b] * HH);
    float4* dst = (float4*)(g_x + b * HH);
    if (threadIdx.x < HH / 4) dst[threadIdx.x] = src[threadIdx.x];
}

// ------------------------ q = sum(4 parts) + bias ------------------------
__global__ void __launch_bounds__(256) k_qbias(const float* __restrict__ query_b) {
    int b = blockIdx.x;
    int j = blockIdx.y * 256 + threadIdx.x;
    float s = query_b[j];
#pragma unroll
    for (int p = 0; p < 4; p++) s += g_partq[p * BB * HH + b * HH + j];
    g_q[b * HH + j] = s;
}

// ------------------------ pipelined M=64 tf32 GEMM with split-K (R6-identical) ------------------------
template <int BN, int S, bool B_NK>
__global__ void __launch_bounds__(256) gemm_pipe(
    const float* __restrict__ A1, const float* __restrict__ A2, int K1, int Ktot,
    const float* __restrict__ B1, const float* __restrict__ B2, int ldb1, int ldb2,
    float* __restrict__ C, int ldc, int N) {
    constexpr int BK  = 16;
    constexpr int AP  = 20;
    constexpr int BPL = BN + 4;     // KN row stride
    constexpr int BNS = 20;         // NK row stride
    constexpr int BSTG = B_NK ? (BN * BNS) : (BK * BPL);
    constexpr int TN = BN / 32;

    extern __shared__ char dsm[];
    float* sA = (float*)dsm;
    float* sB = (float*)(dsm + (size_t)S * 64 * AP * 4);

    const int tid = threadIdx.x, w = tid >> 5;
    const int wm = w & 3, wn = w >> 2;
    const int n0 = blockIdx.x * BN;
    const int Tall = Ktot / BK;
    const int Tper = Tall / gridDim.y;
    const int t0 = blockIdx.y * Tper;
    const bool fullN = (n0 + BN) <= N;
    const bool bAligned = (((ldb1 | ldb2) & 3) == 0);
    C += (size_t)blockIdx.y * 64 * ldc;

    auto issue = [&](int t) {
        int k0 = t * BK;
        const float* Aseg; const float* Bseg; int lda, ldb, kk;
        if (k0 < K1) { Aseg = A1; Bseg = B1; lda = K1;        ldb = ldb1; kk = k0; }
        else         { Aseg = A2; Bseg = B2; lda = Ktot - K1; ldb = ldb2; kk = k0 - K1; }
        int buf = (t - t0) % S;
        int ar = tid >> 2, av = (tid & 3) * 4;
        cp16(smem_u32(&sA[buf * 64 * AP + ar * AP + av]), Aseg + (size_t)ar * lda + kk + av);
        float* sBb = &sB[buf * BSTG];
        if (!B_NK) {
            if (bAligned) {
                constexpr int NV = BN / 4;
                constexpr int TOT = BK * NV;
#pragma unroll
                for (int i = tid; i < TOT; i += 256) {
                    int r = i / NV, c = (i % NV) * 4;
                    cp16(smem_u32(&sBb[r * BPL + c]), Bseg + (size_t)(kk + r) * ldb + n0 + c);
                }
            } else {
                constexpr int TOT = BK * BN;
#pragma unroll
                for (int i = tid; i < TOT; i += 256) {
                    int r = i / BN, c = i % BN;
                    int n = n0 + c;
                    int ok = (fullN || n < N);
                    const float* src = Bseg + (size_t)(kk + r) * ldb + (ok ? n : 0);
                    cp4(smem_u32(&sBb[r * BPL + c]), src, ok ? 4 : 0);
                }
            }
        } else {
            constexpr int TOT = BN * 4;
#pragma unroll
            for (int i = tid; i < TOT; i += 256) {
                int r = i >> 2, c = (i & 3) * 4;
                int n = n0 + r;
                cp16(smem_u32(&sBb[r * BNS + c]), Bseg + (size_t)n * ldb + kk + c);
            }
        }
    };

    wmma::fragment<wmma::matrix_a, 16, 16, 8, wmma::precision::tf32, wmma::row_major> fa;
    wmma::fragment<wmma::accumulator, 16, 16, 8, float> fc[TN];
#pragma unroll
    for (int t = 0; t < TN; t++) wmma::fill_fragment(fc[t], 0.f);

#pragma unroll
    for (int p = 0; p < S - 1; p++) { if (p < Tper) issue(t0 + p); cp_commit(); }

    for (int t = t0; t < t0 + Tper; t++) {
        cp_wait<S - 2>();
        __syncthreads();
        if (t + S - 1 < t0 + Tper) issue(t + S - 1);
        cp_commit();
        int buf = (t - t0) % S;
        float* sAb = &sA[buf * 64 * AP];
        float* sBb = &sB[buf * BSTG];
#pragma unroll
        for (int ks = 0; ks < 2; ks++) {
            wmma::load_matrix_sync(fa, &sAb[wm * 16 * AP + ks * 8], AP);
#pragma unroll
            for (int i = 0; i < fa.num_elements; i++) fa.x[i] = wmma::__float_to_tf32(fa.x[i]);
#pragma unroll
            for (int tt = 0; tt < TN; tt++) {
                int ns = wn * (BN / 2) + tt * 16;
                if (!B_NK) {
                    wmma::fragment<wmma::matrix_b, 16, 16, 8, wmma::precision::tf32, wmma::row_major> fb;
                    wmma::load_matrix_sync(fb, &sBb[ks * 8 * BPL + ns], BPL);
#pragma unroll
                    for (int i = 0; i < fb.num_elements; i++) fb.x[i] = wmma::__float_to_tf32(fb.x[i]);
                    wmma::mma_sync(fc[tt], fa, fb, fc[tt]);
                } else {
                    wmma::fragment<wmma::matrix_b, 16, 16, 8, wmma::precision::tf32, wmma::col_major> fb;
                    wmma::load_matrix_sync(fb, &sBb[ns * BNS + ks * 8], BNS);
#pragma unroll
                    for (int i = 0; i < fb.num_elements; i++) fb.x[i] = wmma::__float_to_tf32(fb.x[i]);
                    wmma::mma_sync(fc[tt], fa, fb, fc[tt]);
                }
            }
        }
    }

    __syncthreads();
    const bool ldc_ok = (ldc & 3) == 0;
    if (ldc_ok && fullN) {
#pragma unroll
        for (int tt = 0; tt < TN; tt++) {
            int nc = n0 + wn * (BN / 2) + tt * 16;
            wmma::store_matrix_sync(&C[(size_t)(wm * 16) * ldc + nc], fc[tt], ldc, wmma::mem_row_major);
        }
    } else {
        constexpr int CP = BN + 4;
        float* sC = sA;
#pragma unroll
        for (int tt = 0; tt < TN; tt++) {
            int ns = wn * (BN / 2) + tt * 16;
            wmma::store_matrix_sync(&sC[(size_t)(wm * 16) * CP + ns], fc[tt], CP, wmma::mem_row_major);
        }
        __syncthreads();
        for (int i = tid; i < 64 * BN; i += 256) {
            int r = i / BN, c = i % BN;
            int n = n0 + c;
            if (n < N) C[(size_t)r * ldc + n] = sC[r * CP + c];
        }
    }
}

// ------------------------ logits GEMM: BN=128, odd-ldb, fused bias + log-softmax pass 1 ------------------------
template <int S>
__global__ void __launch_bounds__(256) gemm_logits(
    const float* __restrict__ A, const float* __restrict__ B,
    const float* __restrict__ bias, float* __restrict__ C, float* __restrict__ lsp) {
    constexpr int BN  = 128;
    constexpr int BK  = 16;
    constexpr int AP  = 20;
    constexpr int BPL = BN + 4;
    constexpr int BSTG = BK * BPL;
    constexpr int TN = 4;
    constexpr int Tper = HH / BK;      // 64

    extern __shared__ char dsm[];
    float* sA = (float*)dsm;
    float* sB = (float*)(dsm + (size_t)S * 64 * AP * 4);

    const int tid = threadIdx.x, w = tid >> 5, lane = tid & 31;
    const int wm = w & 3, wn = w >> 2;
    const int n0 = blockIdx.x * BN;
    const bool fullN = (n0 + BN) <= VV;

    auto issue = [&](int t) {
        int kk = t * BK;
        int buf = t % S;
        int ar = tid >> 2, av = (tid & 3) * 4;
        cp16(smem_u32(&sA[buf * 64 * AP + ar * AP + av]), A + (size_t)ar * HH + kk + av);
        float* sBb = &sB[buf * BSTG];
        if (fullN) {
#pragma unroll
            for (int i = tid; i < BK * BN; i += 256) {
                int r = i / BN, c = i % BN;
                cp4(smem_u32(&sBb[r * BPL + c]), B + (size_t)(kk + r) * VV + n0 + c, 4);
            }
        } else {
#pragma unroll
            for (int i = tid; i < BK * BN; i += 256) {
                int r = i / BN, c = i % BN;
                int n = n0 + c;
                int ok = n < VV;
                const float* src = B + (size_t)(kk + r) * VV + (ok ? n : 0);
                cp4(smem_u32(&sBb[r * BPL + c]), src, ok ? 4 : 0);
            }
        }
    };

    wmma::fragment<wmma::matrix_a, 16, 16, 8, wmma::precision::tf32, wmma::row_major> fa;
    wmma::fragment<wmma::accumulator, 16, 16, 8, float> fc[TN];
#pragma unroll
    for (int t = 0; t < TN; t++) wmma::fill_fragment(fc[t], 0.f);

#pragma unroll
    for (int p = 0; p < S - 1; p++) { issue(p); cp_commit(); }

    for (int t = 0; t < Tper; t++) {
        cp_wait<S - 2>();
        __syncthreads();
        if (t + S - 1 < Tper) issue(t + S - 1);
        cp_commit();
        int buf = t % S;
        float* sAb = &sA[buf * 64 * AP];
        float* sBb = &sB[buf * BSTG];
#pragma unroll
        for (int ks = 0; ks < 2; ks++) {
            wmma::load_matrix_sync(fa, &sAb[wm * 16 * AP + ks * 8], AP);
#pragma unroll
            for (int i = 0; i < fa.num_elements; i++) fa.x[i] = wmma::__float_to_tf32(fa.x[i]);
#pragma unroll
            for (int tt = 0; tt < TN; tt++) {
                int ns = wn * (BN / 2) + tt * 16;
                wmma::fragment<wmma::matrix_b, 16, 16, 8, wmma::precision::tf32, wmma::row_major> fb;
                wmma::load_matrix_sync(fb, &sBb[ks * 8 * BPL + ns], BPL);
#pragma unroll
                for (int i = 0; i < fb.num_elements; i++) fb.x[i] = wmma::__float_to_tf32(fb.x[i]);
                wmma::mma_sync(fc[tt], fa, fb, fc[tt]);
            }
        }
    }

    // staged epilogue: bias add, store, per-row (max, sumexp) partials
    __syncthreads();
    constexpr int CP = BN + 4;
    float* sC = sA;                 // 64*132 = 8448 floats, fits easily
    float* sb = sC + 64 * CP;
#pragma unroll
    for (int tt = 0; tt < TN; tt++) {
        int ns = wn * (BN / 2) + tt * 16;
        wmma::store_matrix_sync(&sC[(size_t)(wm * 16) * CP + ns], fc[tt], CP, wmma::mem_row_major);
    }
    for (int c = tid; c < BN; c += 256) sb[c] = (n0 + c < VV) ? bias[n0 + c] : 0.f;
    __syncthreads();
    for (int i = tid; i < 64 * BN; i += 256) {
        int r = i / BN, c = i % BN;
        int n = n0 + c;
        float v = sC[r * CP + c] + sb[c];
        sC[r * CP + c] = v;
        if (n < VV) C[(size_t)r * VV + n] = v;
    }
    __syncthreads();
    const int nv = min(BN, VV - n0);
#pragma unroll
    for (int rr = 0; rr < 8; rr++) {
        int r = w * 8 + rr;
        float mx = -1e30f;
        for (int c = lane; c < nv; c += 32) mx = fmaxf(mx, sC[r * CP + c]);
#pragma unroll
        for (int o = 16; o > 0; o >>= 1) mx = fmaxf(mx, __shfl_xor_sync(0xffffffffu, mx, o));
        float sm = 0.f;
        for (int c = lane; c < nv; c += 32) sm += __expf(sC[r * CP + c] - mx);
#pragma unroll
        for (int o = 16; o > 0; o >>= 1) sm += __shfl_xor_sync(0xffffffffu, sm, o);
        if (lane == 0) {
            size_t o2 = ((size_t)r * gridDim.x + blockIdx.x) * 2;
            lsp[o2] = mx; lsp[o2 + 1] = sm;
        }
    }
}

// ------------------------ attention scores (sums 4 qk parts) ------------------------
__global__ void __launch_bounds__(256) k_scores(const float* __restrict__ enc) {
    int b = blockIdx.x;
    int tid = threadIdx.x, w = tid >> 5, lane = tid & 31;
    __shared__ __align__(16) float sq[2 * HH];
    for (int j = tid; j < 2 * HH; j += 256) {
        float s = 0.f;
#pragma unroll
        for (int p = 0; p < 4; p++) s += g_partqk[p * BB * 2 * HH + b * 2 * HH + j];
        sq[j] = s;
    }
    __syncthreads();

    for (int ll = w; ll < 10; ll += 8) {
        int l = blockIdx.y * 10 + ll;
        const float* e = enc + ((size_t)b * LL + l) * 2 * HH;
        float acc = 0.f;
        for (int j = lane * 4; j < 2 * HH; j += 128) {
            float4 ev = *(const float4*)(e + j);
            float4 qv = *(const float4*)(sq + j);
            acc += ev.x * qv.x + ev.y * qv.y + ev.z * qv.z + ev.w * qv.w;
        }
#pragma unroll
        for (int o = 16; o > 0; o >>= 1) acc += __shfl_xor_sync(0xffffffffu, acc, o);
        if (lane == 0) g_scores[b * LL + l] = acc * (1.f / HH);
    }
}

// ------------------------ softmax over L=50 ------------------------
__global__ void __launch_bounds__(32) k_softmax(float* __restrict__ out_attn) {
    int b = blockIdx.x, t = threadIdx.x;
    float v0 = (t < LL) ? g_scores[b * LL + t] : -1e30f;
    float v1 = (t + 32 < LL) ? g_scores[b * LL + t + 32] : -1e30f;
    float m = fmaxf(v0, v1);
#pragma unroll
    for (int o = 16; o > 0; o >>= 1) m = fmaxf(m, __shfl_xor_sync(0xffffffffu, m, o));
    float e0 = (t < LL) ? expf(v0 - m) : 0.f;
    float e1 = (t + 32 < LL) ? expf(v1 - m) : 0.f;
    float s = e0 + e1;
#pragma unroll
    for (int o = 16; o > 0; o >>= 1) s += __shfl_xor_sync(0xffffffffu, s, o);
    float inv = 1.f / s;
    if (t < LL)      { g_attn[b * LL + t] = e0 * inv;      if (out_attn) out_attn[b * LL + t] = e0 * inv; }
    if (t + 32 < LL) { g_attn[b * LL + t + 32] = e1 * inv; if (out_attn) out_attn[b * LL + t + 32] = e1 * inv; }
}

// ------------------------ weighted encoder sum ------------------------
__global__ void __launch_bounds__(256) k_wenc(const float* __restrict__ enc) {
    int b = blockIdx.x;
    int j = blockIdx.y * 256 + threadIdx.x;
    __shared__ float at[LL];
    if (threadIdx.x < LL) at[threadIdx.x] = g_attn[b * LL + threadIdx.x];
    __syncthreads();
    const float* e = enc + (size_t)b * LL * 2 * HH + j;
    float acc = 0.f;
#pragma unroll 5
    for (int l = 0; l < LL; l++) acc += at[l] * e[(size_t)l * 2 * HH];
    g_wenc[b * 2 * HH + j] = acc;
}

// ------------------------ LSTM elementwise (sums 8 split-K parts, folds biases) ------------------------
__global__ void __launch_bounds__(256) k_lstm(const float* __restrict__ value_b,
                                              const float* __restrict__ b_x,
                                              const float* __restrict__ b_h,
                                              float* __restrict__ out_h) {
    int b = blockIdx.x;
    int h = blockIdx.y * 256 + threadIdx.x;
    float gf = b_x[h]          + b_h[h];
    float gi = b_x[HH + h]     + b_h[HH + h];
    float gc = b_x[2 * HH + h] + b_h[2 * HH + h];
    float go = b_x[3 * HH + h] + b_h[3 * HH + h];
#pragma unroll
    for (int p = 0; p < 8; p++) {
        const float* g = g_partg + (size_t)p * BB * 4 * HH + b * 4 * HH;
        gf += g[h]; gi += g[HH + h]; gc += g[2 * HH + h]; go += g[3 * HH + h];
    }
    float cp = value_b[h];
#pragma unroll
    for (int p = 0; p < 8; p++) cp += g_partc[p * BB * HH + b * HH + h];

    float f  = 1.f / (1.f + expf(-gf));
    float ig = 1.f / (1.f + expf(-gi));
    float cb = tanhf(gc);
    float o  = 1.f / (1.f + expf(-go));
    float c  = f * cp + ig * cb;
    float hn = o * tanhf(c);
    g_hnext[b * HH + h] = hn;
    if (out_h) out_h[b * HH + h] = hn;
}

// ------------------------ log-softmax reduce over per-block partials ------------------------
__global__ void __launch_bounds__(128) k_lsmred() {
    int b = blockIdx.x, tid = threadIdx.x;
    __shared__ float red[128];
    float M = -1e30f;
    for (int i = tid; i < NBLK; i += 128) M = fmaxf(M, g_lsp[((size_t)b * NBLK + i) * 2]);
    red[tid] = M; __syncthreads();
    for (int s = 64; s > 0; s >>= 1) { if (tid < s) red[tid] = fmaxf(red[tid], red[tid + s]); __syncthreads(); }
    M = red[0]; __syncthreads();
    float S = 0.f;
    for (int i = tid; i < NBLK; i += 128) {
        size_t o2 = ((size_t)b * NBLK + i) * 2;
        S += g_lsp[o2 + 1] * __expf(g_lsp[o2] - M);
    }
    red[tid] = S; __syncthreads();
    for (int s = 64; s > 0; s >>= 1) { if (tid < s) red[tid] += red[tid + s]; __syncthreads(); }
    if (tid == 0) g_lse[b] = M + logf(red[0]);
}

// ------------------------ log-softmax apply (bias already in logits) ------------------------
#define LSM_CH 6283
__global__ void __launch_bounds__(256) k_lsm2(float* __restrict__ logits) {
    int b = blockIdx.x, c = blockIdx.y, tid = threadIdx.x;
    float lse = g_lse[b];
    int start = c * LSM_CH, end = min(start + LSM_CH, VV);
    float* row = logits + (size_t)b * VV;
    for (int v = start + tid; v < end; v += 256) row[v] -= lse;
}

// ------------------------ launch ------------------------
extern "C" void kernel_launch(void* const* d_in, const int* in_sizes, int n_in,
                              void* d_out, int out_size) {
    (void)in_sizes; (void)n_in;
    const int*   idx     = (const int*)  d_in[0];
    const float* h_prev  = (const float*)d_in[1];
    const float* enc     = (const float*)d_in[2];
    const float* emb     = (const float*)d_in[3];
    const float* w_x     = (const float*)d_in[4];
    const float* b_x     = (const float*)d_in[5];
    const float* w_h     = (const float*)d_in[6];
    const float* b_h     = (const float*)d_in[7];
    const float* key_w   = (const float*)d_in[8];
    const float* value_w = (const float*)d_in[10];
    const float* value_b = (const float*)d_in[11];
    const float* query_w = (const float*)d_in[12];
    const float* query_b = (const float*)d_in[13];
    const float* out_w   = (const float*)d_in[14];
    const float* out_b   = (const float*)d_in[15];
    // d_in[9] = key_b: dropped — softmax is shift-invariant in the constant q·key_b.

    float* out      = (float*)d_out;
    float* out_logp = out;
    float* out_h    = nullptr;
    float* out_attn = nullptr;
    long long need = (long long)BB * VV + (long long)BB * HH + (long long)BB * LL;
    if ((long long)out_size >= need) {
        out_h    = out + (size_t)BB * VV;
        out_attn = out_h + (size_t)BB * HH;
    }

    float *p_x, *p_q, *p_wenc, *p_hnext, *p_partq, *p_partqk, *p_partc, *p_partg, *p_lsp;
    cudaGetSymbolAddress((void**)&p_x,      g_x);
    cudaGetSymbolAddress((void**)&p_q,      g_q);
    cudaGetSymbolAddress((void**)&p_wenc,   g_wenc);
    cudaGetSymbolAddress((void**)&p_hnext,  g_hnext);
    cudaGetSymbolAddress((void**)&p_partq,  g_partq);
    cudaGetSymbolAddress((void**)&p_partqk, g_partqk);
    cudaGetSymbolAddress((void**)&p_partc,  g_partc);
    cudaGetSymbolAddress((void**)&p_partg,  g_partg);
    cudaGetSymbolAddress((void**)&p_lsp,    g_lsp);

    constexpr int S = 4;
    const size_t smA      = (size_t)S * 64 * 20 * 4;
    const size_t sm_kn64  = smA + (size_t)S * 16 * 68 * 4;    // 37888
    const size_t sm_nk64  = smA + (size_t)S * 64 * 20 * 4;    // 40960
    const size_t sm_kn128 = smA + (size_t)S * 16 * 132 * 4;   // 54272

    cudaFuncSetAttribute(gemm_pipe<64, S, false>, cudaFuncAttributeMaxDynamicSharedMemorySize, (int)sm_kn64);
    cudaFuncSetAttribute(gemm_pipe<64, S, true>,  cudaFuncAttributeMaxDynamicSharedMemorySize, (int)sm_nk64);
    cudaFuncSetAttribute(gemm_logits<S>,          cudaFuncAttributeMaxDynamicSharedMemorySize, (int)sm_kn128);

    k_gather<<<BB, 256>>>(idx, emb);

    // q partials = h_prev @ query_w  (split-K 4)
    gemm_pipe<64, S, false><<<dim3(HH / 64, 4), 256, sm_kn64>>>(
        h_prev, h_prev, HH, HH, query_w, query_w, HH, HH, p_partq, HH, HH);
    k_qbias<<<dim3(BB, 4), 256>>>(query_b);

    // qk partials = q @ key_w^T  (split-K 4)
    gemm_pipe<64, S, true><<<dim3((2 * HH) / 64, 4), 256, sm_nk64>>>(
        p_q, p_q, HH, HH, key_w, key_w, HH, HH, p_partqk, 2 * HH, 2 * HH);
    // scores (sums 4 qk parts) -> softmax -> weighted enc sum
    k_scores<<<dim3(BB, 5), 256>>>(enc);
    k_softmax<<<BB, 32>>>(out_attn);
    k_wenc<<<dim3(BB, 8), 256>>>(enc);

    // cprev partials = wenc @ value_w  (split-K 8)
    gemm_pipe<64, S, false><<<dim3(HH / 64, 8), 256, sm_kn64>>>(
        p_wenc, p_wenc, 2 * HH, 2 * HH, value_w, value_w, HH, HH, p_partc, HH, HH);
    // gates partials = [x | h_prev] @ [w_x ; w_h]  (split-K 8)
    gemm_pipe<64, S, false><<<dim3((4 * HH) / 64, 8), 256, sm_kn64>>>(
        p_x, h_prev, HH, 2 * HH, w_x, w_h, 4 * HH, 4 * HH, p_partg, 4 * HH, 4 * HH);
    k_lstm<<<dim3(BB, 4), 256>>>(value_b, b_x, b_h, out_h);

    // logits = h_next @ out_w + out_b, fused log-softmax pass 1 (dedicated kernel)
    gemm_logits<S><<<dim3(NBLK, 1), 256, sm_kn128>>>(p_hnext, out_w, out_b, out_logp, p_lsp);
    k_lsmred<<<BB, 128>>>();
    k_lsm2<<<dim3(BB, 8), 256>>>(out_logp);
}